// round 11
// baseline (speedup 1.0000x reference)
#include <cuda_runtime.h>
#include <cuda_fp16.h>
#include <math.h>
#include <stdint.h>

// ===========================================================================
// LocalAttention on sm_100 (portable PTX; mma.sync f16.f32 + ldmatrix):
//   conv3x3(512->768)+ReLU  -> halo-resident fp16 implicit GEMM (occupancy 2)
//   fused flash-style windowed attention (fp16, K/V double-buffered)
//   conv3x3(256->512)+residual -> halo-resident fp16 implicit GEMM (occ 2)
// Conv CTA = 128co x 128px (4x32), 16-ci chunks, 32B smem rows; two CTAs/SM
// hide per-chunk sync + load latency that capped tensor util at 72%.
// ===========================================================================

// ------------------------------- scratch ----------------------------------
__device__ __half g_kt [72 * 1024 * 64];      // K: [m][i][c]
__device__ __half g_qt [72 * 1024 * 64];      // Q: [m][j][c] (pre-scaled 1/8)
__device__ __half g_v  [72 * 64 * 1024];      // V: [m][c][i]
__device__ __half g_xcl[2 * 98 * 98 * 512];   // padded channels-last input
__device__ __half g_ocl[2 * 98 * 98 * 256];   // padded channels-last attn out
__device__ __half g_w1p[9 * 768 * 512];       // W1 [s][co][ci]
__device__ __half g_w2p[9 * 512 * 256];       // W2 [s][co][ci]

// ------------------------------ helpers -----------------------------------
__device__ __forceinline__ uint32_t smem_u32(const void* p) {
    uint32_t a;
    asm("{ .reg .u64 t; cvta.to.shared.u64 t, %1; cvt.u32.u64 %0, t; }" : "=r"(a) : "l"(p));
    return a;
}

#define CP_ASYNC16(sm, gm) \
    asm volatile("cp.async.cg.shared.global [%0], [%1], 16;" :: "r"(sm), "l"(gm))
#define CP_COMMIT() asm volatile("cp.async.commit_group;" ::: "memory")
#define CP_WAIT1()  asm volatile("cp.async.wait_group 1;" ::: "memory")
#define CP_WAIT0()  asm volatile("cp.async.wait_group 0;" ::: "memory")

#define MMA_F16(c0,c1,c2,c3, a0,a1,a2,a3, b0,b1) \
    asm volatile("mma.sync.aligned.m16n8k16.row.col.f32.f16.f16.f32 " \
        "{%0,%1,%2,%3}, {%4,%5,%6,%7}, {%8,%9}, {%0,%1,%2,%3};" \
        : "+f"(c0), "+f"(c1), "+f"(c2), "+f"(c3) \
        : "r"(a0), "r"(a1), "r"(a2), "r"(a3), "r"(b0), "r"(b1))

#define LDSM_X4(r0,r1,r2,r3, a) \
    asm volatile("ldmatrix.sync.aligned.m8n8.x4.shared.b16 {%0,%1,%2,%3}, [%4];" \
        : "=r"(r0), "=r"(r1), "=r"(r2), "=r"(r3) : "r"(a))

// 64B rows (attention): conflict-free ldmatrix swizzle
__device__ __forceinline__ uint32_t swz_addr(uint32_t base, int row, int seg) {
    return base + row * 64 + ((seg ^ ((row >> 1) & 3)) << 4);
}
// 32B rows (conv): rows r and r+4 must differ in 16B unit -> xor with (row>>2)&1
__device__ __forceinline__ uint32_t swz32(uint32_t base, int row, int seg) {
    return base + row * 32 + ((seg ^ ((row >> 2) & 1)) << 4);
}

// ===========================================================================
// Pack kernels (merged launches)
// ===========================================================================
__global__ void fill_border_all_kernel() {
    int idx = blockIdx.x * 256 + threadIdx.x;
    const int N1 = 2 * 388 * 64;
    const int N2 = 2 * 388 * 32;
    __half* out;
    int un, C;
    if (idx < N1) { out = g_xcl; un = 64; C = 512; }
    else if (idx < N1 + N2) { idx -= N1; out = g_ocl; un = 32; C = 256; }
    else return;
    int u = idx % un;
    int cell = (idx / un) % 388;
    int b = idx / (388 * un);
    int h, w;
    if (cell < 98)        { h = 0;  w = cell; }
    else if (cell < 196)  { h = 97; w = cell - 98; }
    else if (cell < 292)  { h = cell - 196 + 1; w = 0; }
    else                  { h = cell - 292 + 1; w = 97; }
    uint4 z = make_uint4(0u, 0u, 0u, 0u);
    ((uint4*)&out[(((size_t)b * 98 + h) * 98 + w) * C])[u] = z;
}

__global__ __launch_bounds__(256) void pack_cl_kernel(const float* __restrict__ in) {
    __shared__ float s[32][97];
    const int h = blockIdx.x, cig = blockIdx.y, b = blockIdx.z;
    const int tid = threadIdx.x;
    for (int e = tid; e < 32 * 96; e += 256) {
        int ci = e / 96, w = e % 96;
        s[ci][w] = in[(((size_t)b * 512 + cig * 32 + ci) * 96 + h) * 96 + w];
    }
    __syncthreads();
    for (int e = tid; e < 96 * 32; e += 256) {
        int w = e >> 5, ci = e & 31;
        g_xcl[(((size_t)b * 98 + h + 1) * 98 + (w + 1)) * 512 + cig * 32 + ci] =
            __float2half_rn(s[ci][w]);
    }
}

__global__ void repack_w_all_kernel(const float* __restrict__ W1,
                                    const float* __restrict__ W2) {
    int idx = blockIdx.x * 256 + threadIdx.x;
    const int N1 = 9 * 768 * 512;
    const int N2 = 9 * 512 * 256;
    if (idx < N1) {
        int s = idx / (768 * 512);
        int rem = idx % (768 * 512);
        int co = rem / 512, ci = rem % 512;
        g_w1p[idx] = __float2half_rn(W1[((size_t)co * 512 + ci) * 9 + s]);
    } else if (idx < N1 + N2) {
        int e = idx - N1;
        int s = e / (512 * 256);
        int rem = e % (512 * 256);
        int co = rem / 256, ci = rem % 256;
        g_w2p[e] = __float2half_rn(W2[((size_t)co * 256 + ci) * 9 + s]);
    }
}

// ===========================================================================
// Halo-resident fp16 implicit-GEMM conv3x3, occupancy 2.
// CTA: D[128 co x 128 px(4x32)]; 8 warps (2M x 4N), warp tile 64co x 32px.
// Per 16-ci chunk: smem A[9][128] rows x 32B + halo B[204] rows x 32B
// (6 x 34 pixels), double buffered (84.8 KB total) -> 2 CTAs/SM.
// MODE 0: bias+ReLU -> fp16 Q(*0.125)/K [m][l][c] and V [m][c][l].
// MODE 1: bias+residual -> out (fp32 exact epilogue).
// ===========================================================================
template <int CIN, int COUT, int MODE>
__global__ void __launch_bounds__(256, 2)
conv_mma_kernel(const float* __restrict__ bias,
                const float* __restrict__ resid,
                float* __restrict__ out)
{
    constexpr int NCH   = CIN / 16;
    constexpr int ABYT  = 9 * 128 * 32;      // 36864 B per buffer
    constexpr int BBYT  = 204 * 32;          // 6528 B per buffer
    constexpr int BUFB  = ABYT + BBYT;       // 43392 B

    const __half* __restrict__ Wp  = (MODE == 0) ? g_w1p : g_w2p;
    const __half* __restrict__ xcl = (MODE == 0) ? g_xcl : g_ocl;
    const int XC = (MODE == 0) ? 512 : 256;

    extern __shared__ __half smh[];
    const uint32_t sb = smem_u32(smh);

    const int tid  = threadIdx.x;
    const int wid  = tid >> 5;
    const int lane = tid & 31;
    const int g = lane >> 2;
    const int t = lane & 3;
    const int wm = wid >> 2;              // 0..1 : co 64-half
    const int wn = wid & 3;               // 0..3 : px row (4 rows in tile)
    const int quad = lane >> 3, rin = lane & 7;

    const int a_rin = (quad & 1) * 8 + rin;   // A row within 16
    const int a_sb  = quad >> 1;              // A 16B-seg half
    const int b_rin = (quad >> 1) * 8 + rin;  // B row within 16
    const int b_sb  = quad & 1;               // B 16B-seg half

    const int pt = blockIdx.x;            // 144 = b(2) x 24 rowbands x 3 colbands
    const int b  = pt / 72;
    const int r  = pt % 72;
    const int h0 = (r / 3) * 4;
    const int w0 = (r % 3) * 32;
    const int co0 = blockIdx.y * 128;

    auto load_stage = [&](int ch, int buf) {
        const int ci0 = ch * 16;
        const uint32_t base = sb + buf * BUFB;
        // A: 9 taps x 128 co rows x 32B  -> 2304 cp16 (9/thread)
#pragma unroll
        for (int i = 0; i < 9; i++) {
            int e = tid + i * 256;
            int row = e >> 1, seg = e & 1;
            int s = row >> 7, cor = row & 127;
            const char* ga = (const char*)
                (Wp + ((size_t)s * COUT + co0 + cor) * CIN + ci0) + seg * 16;
            CP_ASYNC16(swz32(base, row, seg), ga);
        }
        // B halo: 204 pixel rows x 32B -> 408 cp16
#pragma unroll
        for (int i = 0; i < 2; i++) {
            int e = tid + i * 256;
            if (e < 408) {
                int row = e >> 1, seg = e & 1;
                int hr = row / 34, wc = row % 34;
                const char* gb = (const char*)
                    (xcl + (((size_t)(b * 98 + h0 + hr)) * 98 + (w0 + wc)) * XC + ci0) + seg * 16;
                CP_ASYNC16(swz32(base + ABYT, row, seg), gb);
            }
        }
        CP_COMMIT();
    };

    float acc[4][4][4];
#pragma unroll
    for (int mf = 0; mf < 4; mf++)
#pragma unroll
        for (int nf = 0; nf < 4; nf++)
#pragma unroll
            for (int e = 0; e < 4; e++) acc[mf][nf][e] = 0.f;

    load_stage(0, 0);

    for (int ch = 0; ch < NCH; ++ch) {
        const int buf = ch & 1;
        if (ch + 1 < NCH) { load_stage(ch + 1, buf ^ 1); CP_WAIT1(); }
        else              { CP_WAIT0(); }
        __syncthreads();

        const uint32_t abase = sb + buf * BUFB;
        const uint32_t bbase = abase + ABYT;
        const int arow0 = wm * 64 + a_rin;

#pragma unroll 1
        for (int s = 0; s < 9; s++) {
            const int kh = s / 3, kw = s % 3;
            uint32_t bf[2][4];
#pragma unroll
            for (int pf = 0; pf < 2; pf++) {
                int hrow = (wn + kh) * 34 + pf * 16 + kw + b_rin;
                LDSM_X4(bf[pf][0], bf[pf][1], bf[pf][2], bf[pf][3],
                        swz32(bbase, hrow, b_sb));
            }
            const int ab = s * 128 + arow0;
#pragma unroll
            for (int mf = 0; mf < 4; mf++) {
                uint32_t a0, a1, a2, a3;
                LDSM_X4(a0, a1, a2, a3, swz32(abase, ab + mf * 16, a_sb));
#pragma unroll
                for (int pf = 0; pf < 2; pf++) {
                    MMA_F16(acc[mf][2*pf][0], acc[mf][2*pf][1], acc[mf][2*pf][2], acc[mf][2*pf][3],
                            a0, a1, a2, a3, bf[pf][0], bf[pf][1]);
                    MMA_F16(acc[mf][2*pf+1][0], acc[mf][2*pf+1][1], acc[mf][2*pf+1][2], acc[mf][2*pf+1][3],
                            a0, a1, a2, a3, bf[pf][2], bf[pf][3]);
                }
            }
        }
        __syncthreads();
    }

    // ----------------------------- epilogue -------------------------------
#pragma unroll
    for (int mf = 0; mf < 4; mf++) {
#pragma unroll
        for (int half8 = 0; half8 < 2; half8++) {
            const int co_g = co0 + wm * 64 + mf * 16 + g + half8 * 8;
            const float bv = __ldg(&bias[co_g]);
            if (MODE == 0) {
                const int part = co_g >> 8;          // 0=K 1=V 2=Q
                const int hh   = (co_g >> 6) & 3;
                const int cc   = co_g & 63;
                const int mm   = ((b * 9 + (h0 >> 5) * 3 + (w0 >> 5)) << 2) + hh;
                const float qs = (part == 2) ? 0.125f : 1.0f;
#pragma unroll
                for (int nf = 0; nf < 4; nf++) {
                    const int px0 = wn * 32 + nf * 8 + 2 * t;
                    float v0 = qs * fmaxf(acc[mf][nf][half8 * 2 + 0] + bv, 0.f);
                    float v1 = qs * fmaxf(acc[mf][nf][half8 * 2 + 1] + bv, 0.f);
                    const int l0 = ((h0 & 31) + (px0 >> 5)) * 32 + (px0 & 31);
                    if (part == 1) {
                        __half2* dst = (__half2*)(g_v + ((size_t)(mm * 64 + cc)) * 1024 + l0);
                        *dst = __floats2half2_rn(v0, v1);
                    } else {
                        __half* dq = (part ? g_qt : g_kt) + ((size_t)mm * 1024 + l0) * 64 + cc;
                        dq[0]  = __float2half_rn(v0);
                        dq[64] = __float2half_rn(v1);
                    }
                }
            } else {
#pragma unroll
                for (int nf = 0; nf < 4; nf++) {
                    const int px0 = wn * 32 + nf * 8 + 2 * t;
                    const int h = h0 + (px0 >> 5), w = w0 + (px0 & 31);
                    const size_t idx = (((size_t)(b * 512 + co_g) * 96) + h) * 96 + w;
                    float2 rv = *(const float2*)(resid + idx);
                    float2 v;
                    v.x = rv.x + bv + acc[mf][nf][half8 * 2 + 0];
                    v.y = rv.y + bv + acc[mf][nf][half8 * 2 + 1];
                    *(float2*)(out + idx) = v;
                }
            }
        }
    }
}

// ===========================================================================
// Fused flash-style attention, fp16 + ldmatrix, K/V double-buffered
// (unchanged from R10).
// ===========================================================================
__global__ void __launch_bounds__(256, 2) fused_attn_kernel()
{
    constexpr int ST = 72;
    constexpr uint32_t KVB = 64 * ST * 2;
    extern __shared__ __half sh[];
    __half* sQ = sh;
    __half* sK = sQ + 128 * ST;
    __half* sV = sK + 2 * 64 * ST;
    __half* sP = sV + 2 * 64 * ST;
    float* sScale = (float*)(sP + 128 * ST);

    const int m  = blockIdx.y;
    const int jt = blockIdx.x;
    const int tid = threadIdx.x, wid = tid >> 5, lane = tid & 31;
    const int g = lane >> 2, t = lane & 3;
    const int wc = wid >> 2;
    const int wj = wid & 3;
    const uint32_t quad = lane >> 3, rin = lane & 7;
    const uint32_t a_lane = (((quad & 1) * 8 + rin) * ST + (quad >> 1) * 8) * 2;
    const uint32_t b_lane = (((quad >> 1) * 8 + rin) * ST + (quad & 1) * 8) * 2;

    const uint32_t sqb = smem_u32(sQ), skb = smem_u32(sK);
    const uint32_t svb = smem_u32(sV), spb = smem_u32(sP);

    auto load_kv = [&](int ch, int buf) {
        const int i0 = ch * 64;
        const char* Kg = (const char*)(g_kt + ((size_t)m * 1024 + i0) * 64);
        const char* Vg = (const char*)(g_v + (size_t)m * 64 * 1024 + i0);
        const uint32_t kb0 = skb + buf * KVB;
        const uint32_t vb0 = svb + buf * KVB;
        for (int e = tid; e < 512; e += 256) {
            int r = e >> 3, u = e & 7;
            CP_ASYNC16(kb0 + (r * ST) * 2 + u * 16, Kg + r * 128 + u * 16);
        }
        for (int e = tid; e < 512; e += 256) {
            int r = e >> 3, u = e & 7;
            CP_ASYNC16(vb0 + (r * ST) * 2 + u * 16, Vg + r * 2048 + u * 16);
        }
        CP_COMMIT();
    };

    {
        const char* Qg = (const char*)(g_qt + ((size_t)m * 1024 + jt * 128) * 64);
        for (int e = tid; e < 1024; e += 256) {
            int r = e >> 3, u = e & 7;
            CP_ASYNC16(sqb + (r * ST) * 2 + u * 16, Qg + r * 128 + u * 16);
        }
        CP_COMMIT();
    }
    load_kv(0, 0);
    CP_WAIT1();
    __syncthreads();

    uint32_t qf[4][4];
    {
        const uint32_t qa = sqb + (wid * 16 * ST) * 2 + a_lane;
#pragma unroll
        for (int ks = 0; ks < 4; ks++)
            LDSM_X4(qf[ks][0], qf[ks][1], qf[ks][2], qf[ks][3], qa + ks * 32);
    }

    float accO[2][4][4];
#pragma unroll
    for (int mf = 0; mf < 2; mf++)
#pragma unroll
        for (int nf = 0; nf < 4; nf++)
#pragma unroll
            for (int e = 0; e < 4; e++) accO[mf][nf][e] = 0.f;

    float m_run[2] = {-1e30f, -1e30f};
    float l_t[2]   = {0.f, 0.f};
    const int jr = wid * 16 + g;

    for (int ch = 0; ch < 16; ch++) {
        const int buf = ch & 1;
        if (ch + 1 < 16) { load_kv(ch + 1, buf ^ 1); CP_WAIT1(); }
        else             { CP_WAIT0(); }
        __syncthreads();

        float accS[8][4];
#pragma unroll
        for (int nf = 0; nf < 8; nf++)
#pragma unroll
            for (int e = 0; e < 4; e++) accS[nf][e] = 0.f;

        const uint32_t kb = skb + buf * KVB + b_lane;
#pragma unroll
        for (int ks = 0; ks < 4; ks++) {
            const uint32_t kofs = ks * 32;
#pragma unroll
            for (int pf = 0; pf < 4; pf++) {
                uint32_t b0, b1, b2, b3;
                LDSM_X4(b0, b1, b2, b3, kb + pf * 16 * ST * 2 + kofs);
                MMA_F16(accS[2*pf][0], accS[2*pf][1], accS[2*pf][2], accS[2*pf][3],
                        qf[ks][0], qf[ks][1], qf[ks][2], qf[ks][3], b0, b1);
                MMA_F16(accS[2*pf+1][0], accS[2*pf+1][1], accS[2*pf+1][2], accS[2*pf+1][3],
                        qf[ks][0], qf[ks][1], qf[ks][2], qf[ks][3], b2, b3);
            }
        }

        float cmax[2] = {-1e30f, -1e30f};
#pragma unroll
        for (int nf = 0; nf < 8; nf++) {
            cmax[0] = fmaxf(cmax[0], fmaxf(accS[nf][0], accS[nf][1]));
            cmax[1] = fmaxf(cmax[1], fmaxf(accS[nf][2], accS[nf][3]));
        }
#pragma unroll
        for (int o = 1; o <= 2; o <<= 1) {
            cmax[0] = fmaxf(cmax[0], __shfl_xor_sync(0xffffffffu, cmax[0], o));
            cmax[1] = fmaxf(cmax[1], __shfl_xor_sync(0xffffffffu, cmax[1], o));
        }
        float mn0 = fmaxf(m_run[0], cmax[0]);
        float mn1 = fmaxf(m_run[1], cmax[1]);
        float sc0 = __expf(m_run[0] - mn0);
        float sc1 = __expf(m_run[1] - mn1);
        m_run[0] = mn0; m_run[1] = mn1;

        float psum[2] = {0.f, 0.f};
#pragma unroll
        for (int nf = 0; nf < 8; nf++) {
            accS[nf][0] = __expf(accS[nf][0] - mn0);
            accS[nf][1] = __expf(accS[nf][1] - mn0);
            accS[nf][2] = __expf(accS[nf][2] - mn1);
            accS[nf][3] = __expf(accS[nf][3] - mn1);
            psum[0] += accS[nf][0] + accS[nf][1];
            psum[1] += accS[nf][2] + accS[nf][3];
        }
        l_t[0] = l_t[0] * sc0 + psum[0];
        l_t[1] = l_t[1] * sc1 + psum[1];

        if (t == 0) { sScale[jr] = sc0; sScale[jr + 8] = sc1; }
#pragma unroll
        for (int nf = 0; nf < 8; nf++) {
            int ic = nf * 8 + 2 * t;
            *(__half2*)&sP[jr * ST + ic]       = __floats2half2_rn(accS[nf][0], accS[nf][1]);
            *(__half2*)&sP[(jr + 8) * ST + ic] = __floats2half2_rn(accS[nf][2], accS[nf][3]);
        }
        __syncthreads();

#pragma unroll
        for (int nf = 0; nf < 4; nf++) {
            float s0 = sScale[wj * 32 + nf * 8 + 2 * t];
            float s1 = sScale[wj * 32 + nf * 8 + 2 * t + 1];
#pragma unroll
            for (int mf = 0; mf < 2; mf++) {
                accO[mf][nf][0] *= s0; accO[mf][nf][1] *= s1;
                accO[mf][nf][2] *= s0; accO[mf][nf][3] *= s1;
            }
        }
        const uint32_t va = svb + buf * KVB + (wc * 32 * ST) * 2 + a_lane;
        const uint32_t pb = spb + (wj * 32 * ST) * 2 + b_lane;
#pragma unroll
        for (int ks = 0; ks < 4; ks++) {
            const uint32_t kofs = ks * 32;
            uint32_t af[2][4];
#pragma unroll
            for (int mf = 0; mf < 2; mf++)
                LDSM_X4(af[mf][0], af[mf][1], af[mf][2], af[mf][3],
                        va + mf * 16 * ST * 2 + kofs);
#pragma unroll
            for (int pf = 0; pf < 2; pf++) {
                uint32_t b0, b1, b2, b3;
                LDSM_X4(b0, b1, b2, b3, pb + pf * 16 * ST * 2 + kofs);
#pragma unroll
                for (int mf = 0; mf < 2; mf++) {
                    MMA_F16(accO[mf][2*pf][0], accO[mf][2*pf][1], accO[mf][2*pf][2], accO[mf][2*pf][3],
                            af[mf][0], af[mf][1], af[mf][2], af[mf][3], b0, b1);
                    MMA_F16(accO[mf][2*pf+1][0], accO[mf][2*pf+1][1], accO[mf][2*pf+1][2], accO[mf][2*pf+1][3],
                            af[mf][0], af[mf][1], af[mf][2], af[mf][3], b2, b3);
                }
            }
        }
        __syncthreads();
    }

#pragma unroll
    for (int o = 1; o <= 2; o <<= 1) {
        l_t[0] += __shfl_xor_sync(0xffffffffu, l_t[0], o);
        l_t[1] += __shfl_xor_sync(0xffffffffu, l_t[1], o);
    }
    if (t == 0) {
        sScale[jr]     = 1.f / l_t[0];
        sScale[jr + 8] = 1.f / l_t[1];
    }
    __syncthreads();

    const int n = m >> 2, hh = m & 3;
    const int b = n / 9, rem = n % 9;
    const int wh = rem / 3, ww = rem % 3;
#pragma unroll
    for (int nf = 0; nf < 4; nf++) {
#pragma unroll
        for (int e = 0; e < 2; e++) {
            const int jl = wj * 32 + nf * 8 + 2 * t + e;
            const float inv = sScale[jl];
            const int j = jt * 128 + jl;
            const int h = wh * 32 + (j >> 5), w = ww * 32 + (j & 31);
            __half* dst = g_ocl + (((size_t)b * 98 + h + 1) * 98 + (w + 1)) * 256 + hh * 64;
#pragma unroll
            for (int mf = 0; mf < 2; mf++) {
                const int c0 = wc * 32 + mf * 16 + g;
                dst[c0]     = __float2half_rn(accO[mf][nf][0 + e] * inv);
                dst[c0 + 8] = __float2half_rn(accO[mf][nf][2 + e] * inv);
            }
        }
    }
}

// ===========================================================================
extern "C" void kernel_launch(void* const* d_in, const int* in_sizes, int n_in,
                              void* d_out, int out_size)
{
    (void)in_sizes; (void)n_in; (void)out_size;
    const float* x  = (const float*)d_in[0];
    const float* W1 = (const float*)d_in[1];
    const float* b1 = (const float*)d_in[2];
    const float* W2 = (const float*)d_in[3];
    const float* b2 = (const float*)d_in[4];
    float* out = (float*)d_out;

    const int CONV_SMEM = 2 * (9 * 128 * 32 + 204 * 32);   // 86784 B (occ 2)
    cudaFuncSetAttribute(conv_mma_kernel<512, 768, 0>,
                         cudaFuncAttributeMaxDynamicSharedMemorySize, CONV_SMEM);
    cudaFuncSetAttribute(conv_mma_kernel<256, 512, 1>,
                         cudaFuncAttributeMaxDynamicSharedMemorySize, CONV_SMEM);

    const int ATTN_SMEM = (128 + 2 * 64 + 2 * 64 + 128) * 72 * 2 + 128 * 4;  // 74240 B
    cudaFuncSetAttribute(fused_attn_kernel,
                         cudaFuncAttributeMaxDynamicSharedMemorySize, ATTN_SMEM);

    // packs (merged launches)
    const int FB_TOTAL = 2 * 388 * 64 + 2 * 388 * 32;
    fill_border_all_kernel<<<(FB_TOTAL + 255) / 256, 256>>>();
    pack_cl_kernel<<<dim3(96, 16, 2), 256>>>(x);
    const int RW_TOTAL = 9 * 768 * 512 + 9 * 512 * 256;
    repack_w_all_kernel<<<(RW_TOTAL + 255) / 256, 256>>>(W1, W2);

    // conv1 + ReLU -> packed Q/K/V (fp16 mma, halo-resident, occ 2)
    conv_mma_kernel<512, 768, 0><<<dim3(144, 6), 256, CONV_SMEM>>>(b1, nullptr, nullptr);

    // fused attention -> g_ocl (fp16 channels-last conv2 input)
    fused_attn_kernel<<<dim3(8, 72), 256, ATTN_SMEM>>>();

    // conv2 + residual (fp16 mma, halo-resident, occ 2, fp32 epilogue)
    conv_mma_kernel<256, 512, 1><<<dim3(144, 4), 256, CONV_SMEM>>>(b2, x, out);
}

// round 12
// speedup vs baseline: 1.1922x; 1.1922x over previous
#include <cuda_runtime.h>
#include <cuda_fp16.h>
#include <math.h>
#include <stdint.h>

// ===========================================================================
// LocalAttention on sm_100 (portable PTX; mma.sync f16.f32 + ldmatrix):
//   conv3x3(512->768)+ReLU  -> halo-resident fp16 implicit GEMM,
//                              512 threads/CTA (16 warps) for latency hiding
//   fused flash-style windowed attention (fp16, K/V double-buffered)
//   conv3x3(256->512)+residual -> same conv structure
// Conv CTA = 128co x 256px (8x32), 32-ci chunks, 64B smem rows (R10 tiling);
// 16 warps (warp tile 32co x 64px) give 4 warps/SMSP to cover LDSM latency.
// ===========================================================================

// ------------------------------- scratch ----------------------------------
__device__ __half g_kt [72 * 1024 * 64];      // K: [m][i][c]
__device__ __half g_qt [72 * 1024 * 64];      // Q: [m][j][c] (pre-scaled 1/8)
__device__ __half g_v  [72 * 64 * 1024];      // V: [m][c][i]
__device__ __half g_xcl[2 * 98 * 98 * 512];   // padded channels-last input
__device__ __half g_ocl[2 * 98 * 98 * 256];   // padded channels-last attn out
__device__ __half g_w1p[9 * 768 * 512];       // W1 [s][co][ci]
__device__ __half g_w2p[9 * 512 * 256];       // W2 [s][co][ci]

// ------------------------------ helpers -----------------------------------
__device__ __forceinline__ uint32_t smem_u32(const void* p) {
    uint32_t a;
    asm("{ .reg .u64 t; cvta.to.shared.u64 t, %1; cvt.u32.u64 %0, t; }" : "=r"(a) : "l"(p));
    return a;
}

#define CP_ASYNC16(sm, gm) \
    asm volatile("cp.async.cg.shared.global [%0], [%1], 16;" :: "r"(sm), "l"(gm))
#define CP_COMMIT() asm volatile("cp.async.commit_group;" ::: "memory")
#define CP_WAIT1()  asm volatile("cp.async.wait_group 1;" ::: "memory")
#define CP_WAIT0()  asm volatile("cp.async.wait_group 0;" ::: "memory")

#define MMA_F16(c0,c1,c2,c3, a0,a1,a2,a3, b0,b1) \
    asm volatile("mma.sync.aligned.m16n8k16.row.col.f32.f16.f16.f32 " \
        "{%0,%1,%2,%3}, {%4,%5,%6,%7}, {%8,%9}, {%0,%1,%2,%3};" \
        : "+f"(c0), "+f"(c1), "+f"(c2), "+f"(c3) \
        : "r"(a0), "r"(a1), "r"(a2), "r"(a3), "r"(b0), "r"(b1))

#define LDSM_X4(r0,r1,r2,r3, a) \
    asm volatile("ldmatrix.sync.aligned.m8n8.x4.shared.b16 {%0,%1,%2,%3}, [%4];" \
        : "=r"(r0), "=r"(r1), "=r"(r2), "=r"(r3) : "r"(a))

// 64B rows (32 halves), 16B-unit XOR swizzle: conflict-free for ldmatrix
__device__ __forceinline__ uint32_t swz_addr(uint32_t base, int row, int seg) {
    return base + row * 64 + ((seg ^ ((row >> 1) & 3)) << 4);
}

// ===========================================================================
// Pack kernels (merged launches)
// ===========================================================================
__global__ void fill_border_all_kernel() {
    int idx = blockIdx.x * 256 + threadIdx.x;
    const int N1 = 2 * 388 * 64;
    const int N2 = 2 * 388 * 32;
    __half* out;
    int un, C;
    if (idx < N1) { out = g_xcl; un = 64; C = 512; }
    else if (idx < N1 + N2) { idx -= N1; out = g_ocl; un = 32; C = 256; }
    else return;
    int u = idx % un;
    int cell = (idx / un) % 388;
    int b = idx / (388 * un);
    int h, w;
    if (cell < 98)        { h = 0;  w = cell; }
    else if (cell < 196)  { h = 97; w = cell - 98; }
    else if (cell < 292)  { h = cell - 196 + 1; w = 0; }
    else                  { h = cell - 292 + 1; w = 97; }
    uint4 z = make_uint4(0u, 0u, 0u, 0u);
    ((uint4*)&out[(((size_t)b * 98 + h) * 98 + w) * C])[u] = z;
}

__global__ __launch_bounds__(256) void pack_cl_kernel(const float* __restrict__ in) {
    __shared__ float s[32][97];
    const int h = blockIdx.x, cig = blockIdx.y, b = blockIdx.z;
    const int tid = threadIdx.x;
    for (int e = tid; e < 32 * 96; e += 256) {
        int ci = e / 96, w = e % 96;
        s[ci][w] = in[(((size_t)b * 512 + cig * 32 + ci) * 96 + h) * 96 + w];
    }
    __syncthreads();
    for (int e = tid; e < 96 * 32; e += 256) {
        int w = e >> 5, ci = e & 31;
        g_xcl[(((size_t)b * 98 + h + 1) * 98 + (w + 1)) * 512 + cig * 32 + ci] =
            __float2half_rn(s[ci][w]);
    }
}

__global__ void repack_w_all_kernel(const float* __restrict__ W1,
                                    const float* __restrict__ W2) {
    int idx = blockIdx.x * 256 + threadIdx.x;
    const int N1 = 9 * 768 * 512;
    const int N2 = 9 * 512 * 256;
    if (idx < N1) {
        int s = idx / (768 * 512);
        int rem = idx % (768 * 512);
        int co = rem / 512, ci = rem % 512;
        g_w1p[idx] = __float2half_rn(W1[((size_t)co * 512 + ci) * 9 + s]);
    } else if (idx < N1 + N2) {
        int e = idx - N1;
        int s = e / (512 * 256);
        int rem = e % (512 * 256);
        int co = rem / 256, ci = rem % 256;
        g_w2p[e] = __float2half_rn(W2[((size_t)co * 256 + ci) * 9 + s]);
    }
}

// ===========================================================================
// Halo-resident fp16 implicit-GEMM conv3x3, 512 threads (16 warps).
// CTA: D[128 co x 256 px(8x32)]; warp tile 32co x 64px (2M x 8N frags).
// Per 32-ci chunk: smem A[9][128] rows x 64B + halo B[340] rows x 64B
// (10x34 pixels), double buffered (191 KB).
// MODE 0: bias+ReLU -> fp16 Q(*0.125)/K [m][l][c] and V [m][c][l].
// MODE 1: bias+residual -> out (fp32 exact epilogue).
// ===========================================================================
template <int CIN, int COUT, int MODE>
__global__ void __launch_bounds__(512, 1)
conv_mma_kernel(const float* __restrict__ bias,
                const float* __restrict__ resid,
                float* __restrict__ out)
{
    constexpr int NCH   = CIN / 32;
    constexpr int ABYT  = 9 * 128 * 64;      // 73728 B per buffer
    constexpr int BBYT  = 340 * 64;          // 21760 B per buffer
    constexpr int BUFB  = ABYT + BBYT;       // 95488 B

    const __half* __restrict__ Wp  = (MODE == 0) ? g_w1p : g_w2p;
    const __half* __restrict__ xcl = (MODE == 0) ? g_xcl : g_ocl;
    const int XC = (MODE == 0) ? 512 : 256;

    extern __shared__ __half smh[];
    const uint32_t sb = smem_u32(smh);

    const int tid  = threadIdx.x;
    const int wid  = tid >> 5;            // 0..15
    const int lane = tid & 31;
    const int g = lane >> 2;
    const int t = lane & 3;
    const int wm = wid >> 2;              // 0..3 : co 32-quarter
    const int wn = wid & 3;               // 0..3 : px 64-quarter
    const int quad = lane >> 3, rin = lane & 7;

    const int a_rin = (quad & 1) * 8 + rin;   // A row within 16
    const int a_sb  = quad >> 1;              // A 16B-seg half
    const int b_rin = (quad >> 1) * 8 + rin;  // B row within 16
    const int b_sb  = quad & 1;               // B 16B-seg half

    const int pt = blockIdx.x;            // 72 = b(2) x 12 rowbands x 3 colbands
    const int b  = pt / 36;
    const int r  = pt % 36;
    const int h0 = (r / 3) * 8;
    const int w0 = (r % 3) * 32;
    const int co0 = blockIdx.y * 128;

    // halo-row offset of warp's pf-th 16-px block (pf 0..3)
    int pxc[4];
#pragma unroll
    for (int pf = 0; pf < 4; pf++) {
        int n0 = wn * 64 + pf * 16;
        pxc[pf] = (n0 >> 5) * 34 + (n0 & 31);
    }

    auto load_stage = [&](int ch, int buf) {
        const int ci0 = ch * 32;
        const uint32_t base = sb + buf * BUFB;
        // A: 9 taps x 128 co x 64B rows -> 4608 cp16 (9/thread @512)
#pragma unroll
        for (int i = 0; i < 9; i++) {
            int e = tid + i * 512;
            int row = e >> 2, seg = e & 3;
            int s = row >> 7, cor = row & 127;
            const char* ga = (const char*)
                (Wp + ((size_t)s * COUT + co0 + cor) * CIN + ci0) + seg * 16;
            CP_ASYNC16(swz_addr(base, row, seg), ga);
        }
        // B halo: 340 pixel rows x 64B -> 1360 cp16
#pragma unroll
        for (int i = 0; i < 3; i++) {
            int e = tid + i * 512;
            if (e < 1360) {
                int row = e >> 2, seg = e & 3;
                int hr = row / 34, wc = row % 34;
                const char* gb = (const char*)
                    (xcl + (((size_t)(b * 98 + h0 + hr)) * 98 + (w0 + wc)) * XC + ci0) + seg * 16;
                CP_ASYNC16(swz_addr(base + ABYT, row, seg), gb);
            }
        }
        CP_COMMIT();
    };

    float acc[2][8][4];
#pragma unroll
    for (int mf = 0; mf < 2; mf++)
#pragma unroll
        for (int nf = 0; nf < 8; nf++)
#pragma unroll
            for (int e = 0; e < 4; e++) acc[mf][nf][e] = 0.f;

    load_stage(0, 0);

    for (int ch = 0; ch < NCH; ++ch) {
        const int buf = ch & 1;
        if (ch + 1 < NCH) { load_stage(ch + 1, buf ^ 1); CP_WAIT1(); }
        else              { CP_WAIT0(); }
        __syncthreads();

        const uint32_t abase = sb + buf * BUFB;
        const uint32_t bbase = abase + ABYT;
        const int arow0 = wm * 32 + a_rin;

#pragma unroll 1
        for (int s = 0; s < 9; s++) {
            const int kh = s / 3, kw = s % 3;
            const int hb = kh * 34 + kw + b_rin;
            const int ab = s * 128 + arow0;
#pragma unroll
            for (int ks = 0; ks < 2; ks++) {
                const int bseg = ks * 2 + b_sb;
                const int aseg = ks * 2 + a_sb;
                uint32_t bf[4][4];
#pragma unroll
                for (int pf = 0; pf < 4; pf++) {
                    int hrow = hb + pxc[pf];
                    LDSM_X4(bf[pf][0], bf[pf][1], bf[pf][2], bf[pf][3],
                            swz_addr(bbase, hrow, bseg));
                }
#pragma unroll
                for (int mf = 0; mf < 2; mf++) {
                    uint32_t a0, a1, a2, a3;
                    LDSM_X4(a0, a1, a2, a3, swz_addr(abase, ab + mf * 16, aseg));
#pragma unroll
                    for (int pf = 0; pf < 4; pf++) {
                        MMA_F16(acc[mf][2*pf][0], acc[mf][2*pf][1], acc[mf][2*pf][2], acc[mf][2*pf][3],
                                a0, a1, a2, a3, bf[pf][0], bf[pf][1]);
                        MMA_F16(acc[mf][2*pf+1][0], acc[mf][2*pf+1][1], acc[mf][2*pf+1][2], acc[mf][2*pf+1][3],
                                a0, a1, a2, a3, bf[pf][2], bf[pf][3]);
                    }
                }
            }
        }
        __syncthreads();
    }

    // ----------------------------- epilogue -------------------------------
#pragma unroll
    for (int mf = 0; mf < 2; mf++) {
#pragma unroll
        for (int half8 = 0; half8 < 2; half8++) {
            const int co_g = co0 + wm * 32 + mf * 16 + g + half8 * 8;
            const float bv = __ldg(&bias[co_g]);
            if (MODE == 0) {
                const int part = co_g >> 8;          // 0=K 1=V 2=Q
                const int hh   = (co_g >> 6) & 3;
                const int cc   = co_g & 63;
                const int mm   = ((b * 9 + (h0 >> 5) * 3 + (w0 >> 5)) << 2) + hh;
                const float qs = (part == 2) ? 0.125f : 1.0f;
#pragma unroll
                for (int nf = 0; nf < 8; nf++) {
                    const int px0 = wn * 64 + nf * 8 + 2 * t;
                    float v0 = qs * fmaxf(acc[mf][nf][half8 * 2 + 0] + bv, 0.f);
                    float v1 = qs * fmaxf(acc[mf][nf][half8 * 2 + 1] + bv, 0.f);
                    const int l0 = ((h0 & 31) + (px0 >> 5)) * 32 + (px0 & 31);
                    if (part == 1) {
                        __half2* dst = (__half2*)(g_v + ((size_t)(mm * 64 + cc)) * 1024 + l0);
                        *dst = __floats2half2_rn(v0, v1);
                    } else {
                        __half* dq = (part ? g_qt : g_kt) + ((size_t)mm * 1024 + l0) * 64 + cc;
                        dq[0]  = __float2half_rn(v0);
                        dq[64] = __float2half_rn(v1);
                    }
                }
            } else {
#pragma unroll
                for (int nf = 0; nf < 8; nf++) {
                    const int px0 = wn * 64 + nf * 8 + 2 * t;
                    const int h = h0 + (px0 >> 5), w = w0 + (px0 & 31);
                    const size_t idx = (((size_t)(b * 512 + co_g) * 96) + h) * 96 + w;
                    float2 rv = *(const float2*)(resid + idx);
                    float2 v;
                    v.x = rv.x + bv + acc[mf][nf][half8 * 2 + 0];
                    v.y = rv.y + bv + acc[mf][nf][half8 * 2 + 1];
                    *(float2*)(out + idx) = v;
                }
            }
        }
    }
}

// ===========================================================================
// Fused flash-style attention, fp16 + ldmatrix, K/V double-buffered
// (unchanged from R10).
// ===========================================================================
__global__ void __launch_bounds__(256, 2) fused_attn_kernel()
{
    constexpr int ST = 72;
    constexpr uint32_t KVB = 64 * ST * 2;
    extern __shared__ __half sh[];
    __half* sQ = sh;
    __half* sK = sQ + 128 * ST;
    __half* sV = sK + 2 * 64 * ST;
    __half* sP = sV + 2 * 64 * ST;
    float* sScale = (float*)(sP + 128 * ST);

    const int m  = blockIdx.y;
    const int jt = blockIdx.x;
    const int tid = threadIdx.x, wid = tid >> 5, lane = tid & 31;
    const int g = lane >> 2, t = lane & 3;
    const int wc = wid >> 2;
    const int wj = wid & 3;
    const uint32_t quad = lane >> 3, rin = lane & 7;
    const uint32_t a_lane = (((quad & 1) * 8 + rin) * ST + (quad >> 1) * 8) * 2;
    const uint32_t b_lane = (((quad >> 1) * 8 + rin) * ST + (quad & 1) * 8) * 2;

    const uint32_t sqb = smem_u32(sQ), skb = smem_u32(sK);
    const uint32_t svb = smem_u32(sV), spb = smem_u32(sP);

    auto load_kv = [&](int ch, int buf) {
        const int i0 = ch * 64;
        const char* Kg = (const char*)(g_kt + ((size_t)m * 1024 + i0) * 64);
        const char* Vg = (const char*)(g_v + (size_t)m * 64 * 1024 + i0);
        const uint32_t kb0 = skb + buf * KVB;
        const uint32_t vb0 = svb + buf * KVB;
        for (int e = tid; e < 512; e += 256) {
            int r = e >> 3, u = e & 7;
            CP_ASYNC16(kb0 + (r * ST) * 2 + u * 16, Kg + r * 128 + u * 16);
        }
        for (int e = tid; e < 512; e += 256) {
            int r = e >> 3, u = e & 7;
            CP_ASYNC16(vb0 + (r * ST) * 2 + u * 16, Vg + r * 2048 + u * 16);
        }
        CP_COMMIT();
    };

    {
        const char* Qg = (const char*)(g_qt + ((size_t)m * 1024 + jt * 128) * 64);
        for (int e = tid; e < 1024; e += 256) {
            int r = e >> 3, u = e & 7;
            CP_ASYNC16(sqb + (r * ST) * 2 + u * 16, Qg + r * 128 + u * 16);
        }
        CP_COMMIT();
    }
    load_kv(0, 0);
    CP_WAIT1();
    __syncthreads();

    uint32_t qf[4][4];
    {
        const uint32_t qa = sqb + (wid * 16 * ST) * 2 + a_lane;
#pragma unroll
        for (int ks = 0; ks < 4; ks++)
            LDSM_X4(qf[ks][0], qf[ks][1], qf[ks][2], qf[ks][3], qa + ks * 32);
    }

    float accO[2][4][4];
#pragma unroll
    for (int mf = 0; mf < 2; mf++)
#pragma unroll
        for (int nf = 0; nf < 4; nf++)
#pragma unroll
            for (int e = 0; e < 4; e++) accO[mf][nf][e] = 0.f;

    float m_run[2] = {-1e30f, -1e30f};
    float l_t[2]   = {0.f, 0.f};
    const int jr = wid * 16 + g;

    for (int ch = 0; ch < 16; ch++) {
        const int buf = ch & 1;
        if (ch + 1 < 16) { load_kv(ch + 1, buf ^ 1); CP_WAIT1(); }
        else             { CP_WAIT0(); }
        __syncthreads();

        float accS[8][4];
#pragma unroll
        for (int nf = 0; nf < 8; nf++)
#pragma unroll
            for (int e = 0; e < 4; e++) accS[nf][e] = 0.f;

        const uint32_t kb = skb + buf * KVB + b_lane;
#pragma unroll
        for (int ks = 0; ks < 4; ks++) {
            const uint32_t kofs = ks * 32;
#pragma unroll
            for (int pf = 0; pf < 4; pf++) {
                uint32_t b0, b1, b2, b3;
                LDSM_X4(b0, b1, b2, b3, kb + pf * 16 * ST * 2 + kofs);
                MMA_F16(accS[2*pf][0], accS[2*pf][1], accS[2*pf][2], accS[2*pf][3],
                        qf[ks][0], qf[ks][1], qf[ks][2], qf[ks][3], b0, b1);
                MMA_F16(accS[2*pf+1][0], accS[2*pf+1][1], accS[2*pf+1][2], accS[2*pf+1][3],
                        qf[ks][0], qf[ks][1], qf[ks][2], qf[ks][3], b2, b3);
            }
        }

        float cmax[2] = {-1e30f, -1e30f};
#pragma unroll
        for (int nf = 0; nf < 8; nf++) {
            cmax[0] = fmaxf(cmax[0], fmaxf(accS[nf][0], accS[nf][1]));
            cmax[1] = fmaxf(cmax[1], fmaxf(accS[nf][2], accS[nf][3]));
        }
#pragma unroll
        for (int o = 1; o <= 2; o <<= 1) {
            cmax[0] = fmaxf(cmax[0], __shfl_xor_sync(0xffffffffu, cmax[0], o));
            cmax[1] = fmaxf(cmax[1], __shfl_xor_sync(0xffffffffu, cmax[1], o));
        }
        float mn0 = fmaxf(m_run[0], cmax[0]);
        float mn1 = fmaxf(m_run[1], cmax[1]);
        float sc0 = __expf(m_run[0] - mn0);
        float sc1 = __expf(m_run[1] - mn1);
        m_run[0] = mn0; m_run[1] = mn1;

        float psum[2] = {0.f, 0.f};
#pragma unroll
        for (int nf = 0; nf < 8; nf++) {
            accS[nf][0] = __expf(accS[nf][0] - mn0);
            accS[nf][1] = __expf(accS[nf][1] - mn0);
            accS[nf][2] = __expf(accS[nf][2] - mn1);
            accS[nf][3] = __expf(accS[nf][3] - mn1);
            psum[0] += accS[nf][0] + accS[nf][1];
            psum[1] += accS[nf][2] + accS[nf][3];
        }
        l_t[0] = l_t[0] * sc0 + psum[0];
        l_t[1] = l_t[1] * sc1 + psum[1];

        if (t == 0) { sScale[jr] = sc0; sScale[jr + 8] = sc1; }
#pragma unroll
        for (int nf = 0; nf < 8; nf++) {
            int ic = nf * 8 + 2 * t;
            *(__half2*)&sP[jr * ST + ic]       = __floats2half2_rn(accS[nf][0], accS[nf][1]);
            *(__half2*)&sP[(jr + 8) * ST + ic] = __floats2half2_rn(accS[nf][2], accS[nf][3]);
        }
        __syncthreads();

#pragma unroll
        for (int nf = 0; nf < 4; nf++) {
            float s0 = sScale[wj * 32 + nf * 8 + 2 * t];
            float s1 = sScale[wj * 32 + nf * 8 + 2 * t + 1];
#pragma unroll
            for (int mf = 0; mf < 2; mf++) {
                accO[mf][nf][0] *= s0; accO[mf][nf][1] *= s1;
                accO[mf][nf][2] *= s0; accO[mf][nf][3] *= s1;
            }
        }
        const uint32_t va = svb + buf * KVB + (wc * 32 * ST) * 2 + a_lane;
        const uint32_t pb = spb + (wj * 32 * ST) * 2 + b_lane;
#pragma unroll
        for (int ks = 0; ks < 4; ks++) {
            const uint32_t kofs = ks * 32;
            uint32_t af[2][4];
#pragma unroll
            for (int mf = 0; mf < 2; mf++)
                LDSM_X4(af[mf][0], af[mf][1], af[mf][2], af[mf][3],
                        va + mf * 16 * ST * 2 + kofs);
#pragma unroll
            for (int pf = 0; pf < 2; pf++) {
                uint32_t b0, b1, b2, b3;
                LDSM_X4(b0, b1, b2, b3, pb + pf * 16 * ST * 2 + kofs);
#pragma unroll
                for (int mf = 0; mf < 2; mf++) {
                    MMA_F16(accO[mf][2*pf][0], accO[mf][2*pf][1], accO[mf][2*pf][2], accO[mf][2*pf][3],
                            af[mf][0], af[mf][1], af[mf][2], af[mf][3], b0, b1);
                    MMA_F16(accO[mf][2*pf+1][0], accO[mf][2*pf+1][1], accO[mf][2*pf+1][2], accO[mf][2*pf+1][3],
                            af[mf][0], af[mf][1], af[mf][2], af[mf][3], b2, b3);
                }
            }
        }
        __syncthreads();
    }

#pragma unroll
    for (int o = 1; o <= 2; o <<= 1) {
        l_t[0] += __shfl_xor_sync(0xffffffffu, l_t[0], o);
        l_t[1] += __shfl_xor_sync(0xffffffffu, l_t[1], o);
    }
    if (t == 0) {
        sScale[jr]     = 1.f / l_t[0];
        sScale[jr + 8] = 1.f / l_t[1];
    }
    __syncthreads();

    const int n = m >> 2, hh = m & 3;
    const int b = n / 9, rem = n % 9;
    const int wh = rem / 3, ww = rem % 3;
#pragma unroll
    for (int nf = 0; nf < 4; nf++) {
#pragma unroll
        for (int e = 0; e < 2; e++) {
            const int jl = wj * 32 + nf * 8 + 2 * t + e;
            const float inv = sScale[jl];
            const int j = jt * 128 + jl;
            const int h = wh * 32 + (j >> 5), w = ww * 32 + (j & 31);
            __half* dst = g_ocl + (((size_t)b * 98 + h + 1) * 98 + (w + 1)) * 256 + hh * 64;
#pragma unroll
            for (int mf = 0; mf < 2; mf++) {
                const int c0 = wc * 32 + mf * 16 + g;
                dst[c0]     = __float2half_rn(accO[mf][nf][0 + e] * inv);
                dst[c0 + 8] = __float2half_rn(accO[mf][nf][2 + e] * inv);
            }
        }
    }
}

// ===========================================================================
extern "C" void kernel_launch(void* const* d_in, const int* in_sizes, int n_in,
                              void* d_out, int out_size)
{
    (void)in_sizes; (void)n_in; (void)out_size;
    const float* x  = (const float*)d_in[0];
    const float* W1 = (const float*)d_in[1];
    const float* b1 = (const float*)d_in[2];
    const float* W2 = (const float*)d_in[3];
    const float* b2 = (const float*)d_in[4];
    float* out = (float*)d_out;

    const int CONV_SMEM = 2 * (9 * 128 * 64 + 340 * 64);   // 190976 B
    cudaFuncSetAttribute(conv_mma_kernel<512, 768, 0>,
                         cudaFuncAttributeMaxDynamicSharedMemorySize, CONV_SMEM);
    cudaFuncSetAttribute(conv_mma_kernel<256, 512, 1>,
                         cudaFuncAttributeMaxDynamicSharedMemorySize, CONV_SMEM);

    const int ATTN_SMEM = (128 + 2 * 64 + 2 * 64 + 128) * 72 * 2 + 128 * 4;  // 74240 B
    cudaFuncSetAttribute(fused_attn_kernel,
                         cudaFuncAttributeMaxDynamicSharedMemorySize, ATTN_SMEM);

    // packs (merged launches)
    const int FB_TOTAL = 2 * 388 * 64 + 2 * 388 * 32;
    fill_border_all_kernel<<<(FB_TOTAL + 255) / 256, 256>>>();
    pack_cl_kernel<<<dim3(96, 16, 2), 256>>>(x);
    const int RW_TOTAL = 9 * 768 * 512 + 9 * 512 * 256;
    repack_w_all_kernel<<<(RW_TOTAL + 255) / 256, 256>>>(W1, W2);

    // conv1 + ReLU -> packed Q/K/V (fp16 mma, halo-resident, 512 threads)
    conv_mma_kernel<512, 768, 0><<<dim3(72, 6), 512, CONV_SMEM>>>(b1, nullptr, nullptr);

    // fused attention -> g_ocl (fp16 channels-last conv2 input)
    fused_attn_kernel<<<dim3(8, 72), 256, ATTN_SMEM>>>();

    // conv2 + residual (fp16 mma, halo-resident, 512 threads, fp32 epilogue)
    conv_mma_kernel<256, 512, 1><<<dim3(72, 4), 512, CONV_SMEM>>>(b2, x, out);
}

// round 13
// speedup vs baseline: 1.2572x; 1.0545x over previous
#include <cuda_runtime.h>
#include <cuda_fp16.h>
#include <math.h>
#include <stdint.h>

// ===========================================================================
// LocalAttention on sm_100 (portable PTX; mma.sync f16.f32 + ldmatrix):
//   conv3x3(512->768)+ReLU  -> halo-resident fp16 implicit GEMM (R10 tiling)
//   fused flash-style windowed attention (fp16, K/V double-buffered)
//   conv3x3(256->512)+residual -> halo-resident fp16 implicit GEMM
// Conv CTA = 128co x 256px (8x32), 256 threads, 32-ci chunks; tap loop
// unrolled x3 so ptxas overlaps next tap's ldmatrix under current MMAs.
// ===========================================================================

// ------------------------------- scratch ----------------------------------
__device__ __half g_kt [72 * 1024 * 64];      // K: [m][i][c]
__device__ __half g_qt [72 * 1024 * 64];      // Q: [m][j][c] (pre-scaled 1/8)
__device__ __half g_v  [72 * 64 * 1024];      // V: [m][c][i]
__device__ __half g_xcl[2 * 98 * 98 * 512];   // padded channels-last input
__device__ __half g_ocl[2 * 98 * 98 * 256];   // padded channels-last attn out
__device__ __half g_w1p[9 * 768 * 512];       // W1 [s][co][ci]
__device__ __half g_w2p[9 * 512 * 256];       // W2 [s][co][ci]

// ------------------------------ helpers -----------------------------------
__device__ __forceinline__ uint32_t smem_u32(const void* p) {
    uint32_t a;
    asm("{ .reg .u64 t; cvta.to.shared.u64 t, %1; cvt.u32.u64 %0, t; }" : "=r"(a) : "l"(p));
    return a;
}

#define CP_ASYNC16(sm, gm) \
    asm volatile("cp.async.cg.shared.global [%0], [%1], 16;" :: "r"(sm), "l"(gm))
#define CP_COMMIT() asm volatile("cp.async.commit_group;" ::: "memory")
#define CP_WAIT1()  asm volatile("cp.async.wait_group 1;" ::: "memory")
#define CP_WAIT0()  asm volatile("cp.async.wait_group 0;" ::: "memory")

#define MMA_F16(c0,c1,c2,c3, a0,a1,a2,a3, b0,b1) \
    asm volatile("mma.sync.aligned.m16n8k16.row.col.f32.f16.f16.f32 " \
        "{%0,%1,%2,%3}, {%4,%5,%6,%7}, {%8,%9}, {%0,%1,%2,%3};" \
        : "+f"(c0), "+f"(c1), "+f"(c2), "+f"(c3) \
        : "r"(a0), "r"(a1), "r"(a2), "r"(a3), "r"(b0), "r"(b1))

#define LDSM_X4(r0,r1,r2,r3, a) \
    asm volatile("ldmatrix.sync.aligned.m8n8.x4.shared.b16 {%0,%1,%2,%3}, [%4];" \
        : "=r"(r0), "=r"(r1), "=r"(r2), "=r"(r3) : "r"(a))

// 64B rows (32 halves), 16B-unit XOR swizzle: conflict-free for ldmatrix
__device__ __forceinline__ uint32_t swz_addr(uint32_t base, int row, int seg) {
    return base + row * 64 + ((seg ^ ((row >> 1) & 3)) << 4);
}

// ===========================================================================
// Pack kernels (merged launches)
// ===========================================================================
__global__ void fill_border_all_kernel() {
    int idx = blockIdx.x * 256 + threadIdx.x;
    const int N1 = 2 * 388 * 64;
    const int N2 = 2 * 388 * 32;
    __half* out;
    int un, C;
    if (idx < N1) { out = g_xcl; un = 64; C = 512; }
    else if (idx < N1 + N2) { idx -= N1; out = g_ocl; un = 32; C = 256; }
    else return;
    int u = idx % un;
    int cell = (idx / un) % 388;
    int b = idx / (388 * un);
    int h, w;
    if (cell < 98)        { h = 0;  w = cell; }
    else if (cell < 196)  { h = 97; w = cell - 98; }
    else if (cell < 292)  { h = cell - 196 + 1; w = 0; }
    else                  { h = cell - 292 + 1; w = 97; }
    uint4 z = make_uint4(0u, 0u, 0u, 0u);
    ((uint4*)&out[(((size_t)b * 98 + h) * 98 + w) * C])[u] = z;
}

__global__ __launch_bounds__(256) void pack_cl_kernel(const float* __restrict__ in) {
    __shared__ float s[32][97];
    const int h = blockIdx.x, cig = blockIdx.y, b = blockIdx.z;
    const int tid = threadIdx.x;
    for (int e = tid; e < 32 * 96; e += 256) {
        int ci = e / 96, w = e % 96;
        s[ci][w] = in[(((size_t)b * 512 + cig * 32 + ci) * 96 + h) * 96 + w];
    }
    __syncthreads();
    for (int e = tid; e < 96 * 32; e += 256) {
        int w = e >> 5, ci = e & 31;
        g_xcl[(((size_t)b * 98 + h + 1) * 98 + (w + 1)) * 512 + cig * 32 + ci] =
            __float2half_rn(s[ci][w]);
    }
}

__global__ void repack_w_all_kernel(const float* __restrict__ W1,
                                    const float* __restrict__ W2) {
    int idx = blockIdx.x * 256 + threadIdx.x;
    const int N1 = 9 * 768 * 512;
    const int N2 = 9 * 512 * 256;
    if (idx < N1) {
        int s = idx / (768 * 512);
        int rem = idx % (768 * 512);
        int co = rem / 512, ci = rem % 512;
        g_w1p[idx] = __float2half_rn(W1[((size_t)co * 512 + ci) * 9 + s]);
    } else if (idx < N1 + N2) {
        int e = idx - N1;
        int s = e / (512 * 256);
        int rem = e % (512 * 256);
        int co = rem / 256, ci = rem % 256;
        g_w2p[e] = __float2half_rn(W2[((size_t)co * 256 + ci) * 9 + s]);
    }
}

// ===========================================================================
// Halo-resident fp16 implicit-GEMM conv3x3 (R10 tiling, tap loop unroll 3).
// CTA: D[128 co x 256 px(8x32)]; 8 warps (2M x 4N), warp tile 64co x 64px.
// Per 32-ci chunk: smem A[9][128][32] (all taps) + halo B[340][32]
// (10x34 pixels); MMA sweeps all 9 taps against the resident halo.
// MODE 0: bias+ReLU -> fp16 Q(*0.125)/K [m][l][c] and V [m][c][l].
// MODE 1: bias+residual -> out (fp32 exact epilogue).
// ===========================================================================
template <int CIN, int COUT, int MODE>
__global__ void __launch_bounds__(256, 1)
conv_mma_kernel(const float* __restrict__ bias,
                const float* __restrict__ resid,
                float* __restrict__ out)
{
    constexpr int NCH   = CIN / 32;
    constexpr int ABYT  = 9 * 128 * 64;      // 73728 B per buffer
    constexpr int BBYT  = 340 * 64;          // 21760 B per buffer
    constexpr int BUFB  = ABYT + BBYT;       // 95488 B

    const __half* __restrict__ Wp  = (MODE == 0) ? g_w1p : g_w2p;
    const __half* __restrict__ xcl = (MODE == 0) ? g_xcl : g_ocl;
    const int XC = (MODE == 0) ? 512 : 256;

    extern __shared__ __half smh[];
    const uint32_t sb = smem_u32(smh);

    const int tid  = threadIdx.x;
    const int wid  = tid >> 5;
    const int lane = tid & 31;
    const int g = lane >> 2;
    const int t = lane & 3;
    const int wm = wid >> 2;              // 0..1 : co 64-half
    const int wn = wid & 3;               // 0..3 : px 64-quarter
    const int quad = lane >> 3, rin = lane & 7;

    const int a_rin = (quad & 1) * 8 + rin;
    const int a_sb  = quad >> 1;
    const int b_rin = (quad >> 1) * 8 + rin;
    const int b_sb  = quad & 1;

    const int pt = blockIdx.x;            // 72 = b(2) x 12 rowbands x 3 colbands
    const int b  = pt / 36;
    const int r  = pt % 36;
    const int h0 = (r / 3) * 8;
    const int w0 = (r % 3) * 32;
    const int co0 = blockIdx.y * 128;

    int pxc[4];
#pragma unroll
    for (int pf = 0; pf < 4; pf++) {
        int n0 = wn * 64 + pf * 16;
        pxc[pf] = (n0 >> 5) * 34 + (n0 & 31);
    }

    auto load_stage = [&](int ch, int buf) {
        const int ci0 = ch * 32;
        const uint32_t base = sb + buf * BUFB;
#pragma unroll
        for (int i = 0; i < 18; i++) {
            int e = tid + i * 256;
            int row = e >> 2, seg = e & 3;
            int s = row >> 7, cor = row & 127;
            const char* ga = (const char*)
                (Wp + ((size_t)s * COUT + co0 + cor) * CIN + ci0) + seg * 16;
            CP_ASYNC16(swz_addr(base, row, seg), ga);
        }
#pragma unroll
        for (int i = 0; i < 6; i++) {
            int e = tid + i * 256;
            if (e < 1360) {
                int row = e >> 2, seg = e & 3;
                int hr = row / 34, wc = row % 34;
                const char* gb = (const char*)
                    (xcl + (((size_t)(b * 98 + h0 + hr)) * 98 + (w0 + wc)) * XC + ci0) + seg * 16;
                CP_ASYNC16(swz_addr(base + ABYT, row, seg), gb);
            }
        }
        CP_COMMIT();
    };

    float acc[4][8][4];
#pragma unroll
    for (int mf = 0; mf < 4; mf++)
#pragma unroll
        for (int nf = 0; nf < 8; nf++)
#pragma unroll
            for (int e = 0; e < 4; e++) acc[mf][nf][e] = 0.f;

    load_stage(0, 0);

    for (int ch = 0; ch < NCH; ++ch) {
        const int buf = ch & 1;
        if (ch + 1 < NCH) { load_stage(ch + 1, buf ^ 1); CP_WAIT1(); }
        else              { CP_WAIT0(); }
        __syncthreads();

        const uint32_t abase = sb + buf * BUFB;
        const uint32_t bbase = abase + ABYT;
        const int arow0 = wm * 64 + a_rin;

#pragma unroll 3
        for (int s = 0; s < 9; s++) {
            const int kh = s / 3, kw = s % 3;
            const int hb = kh * 34 + kw + b_rin;
            const int ab = s * 128 + arow0;
#pragma unroll
            for (int ks = 0; ks < 2; ks++) {
                const int bseg = ks * 2 + b_sb;
                const int aseg = ks * 2 + a_sb;
                uint32_t bf[4][4];
#pragma unroll
                for (int pf = 0; pf < 4; pf++) {
                    int hrow = hb + pxc[pf];
                    LDSM_X4(bf[pf][0], bf[pf][1], bf[pf][2], bf[pf][3],
                            swz_addr(bbase, hrow, bseg));
                }
#pragma unroll
                for (int mf = 0; mf < 4; mf++) {
                    uint32_t a0, a1, a2, a3;
                    LDSM_X4(a0, a1, a2, a3, swz_addr(abase, ab + mf * 16, aseg));
#pragma unroll
                    for (int pf = 0; pf < 4; pf++) {
                        MMA_F16(acc[mf][2*pf][0], acc[mf][2*pf][1], acc[mf][2*pf][2], acc[mf][2*pf][3],
                                a0, a1, a2, a3, bf[pf][0], bf[pf][1]);
                        MMA_F16(acc[mf][2*pf+1][0], acc[mf][2*pf+1][1], acc[mf][2*pf+1][2], acc[mf][2*pf+1][3],
                                a0, a1, a2, a3, bf[pf][2], bf[pf][3]);
                    }
                }
            }
        }
        __syncthreads();
    }

    // ----------------------------- epilogue -------------------------------
#pragma unroll
    for (int mf = 0; mf < 4; mf++) {
#pragma unroll
        for (int half8 = 0; half8 < 2; half8++) {
            const int co_g = co0 + wm * 64 + mf * 16 + g + half8 * 8;
            const float bv = __ldg(&bias[co_g]);
            if (MODE == 0) {
                const int part = co_g >> 8;          // 0=K 1=V 2=Q
                const int hh   = (co_g >> 6) & 3;
                const int cc   = co_g & 63;
                const int mm   = ((b * 9 + (h0 >> 5) * 3 + (w0 >> 5)) << 2) + hh;
                const float qs = (part == 2) ? 0.125f : 1.0f;
#pragma unroll
                for (int nf = 0; nf < 8; nf++) {
                    const int px0 = wn * 64 + nf * 8 + 2 * t;
                    float v0 = qs * fmaxf(acc[mf][nf][half8 * 2 + 0] + bv, 0.f);
                    float v1 = qs * fmaxf(acc[mf][nf][half8 * 2 + 1] + bv, 0.f);
                    const int l0 = ((h0 & 31) + (px0 >> 5)) * 32 + (px0 & 31);
                    if (part == 1) {
                        __half2* dst = (__half2*)(g_v + ((size_t)(mm * 64 + cc)) * 1024 + l0);
                        *dst = __floats2half2_rn(v0, v1);
                    } else {
                        __half* dq = (part ? g_qt : g_kt) + ((size_t)mm * 1024 + l0) * 64 + cc;
                        dq[0]  = __float2half_rn(v0);
                        dq[64] = __float2half_rn(v1);
                    }
                }
            } else {
#pragma unroll
                for (int nf = 0; nf < 8; nf++) {
                    const int px0 = wn * 64 + nf * 8 + 2 * t;
                    const int h = h0 + (px0 >> 5), w = w0 + (px0 & 31);
                    const size_t idx = (((size_t)(b * 512 + co_g) * 96) + h) * 96 + w;
                    float2 rv = *(const float2*)(resid + idx);
                    float2 v;
                    v.x = rv.x + bv + acc[mf][nf][half8 * 2 + 0];
                    v.y = rv.y + bv + acc[mf][nf][half8 * 2 + 1];
                    *(float2*)(out + idx) = v;
                }
            }
        }
    }
}

// ===========================================================================
// Fused flash-style attention, fp16 + ldmatrix, K/V double-buffered
// (unchanged from R10).
// ===========================================================================
__global__ void __launch_bounds__(256, 2) fused_attn_kernel()
{
    constexpr int ST = 72;
    constexpr uint32_t KVB = 64 * ST * 2;
    extern __shared__ __half sh[];
    __half* sQ = sh;
    __half* sK = sQ + 128 * ST;
    __half* sV = sK + 2 * 64 * ST;
    __half* sP = sV + 2 * 64 * ST;
    float* sScale = (float*)(sP + 128 * ST);

    const int m  = blockIdx.y;
    const int jt = blockIdx.x;
    const int tid = threadIdx.x, wid = tid >> 5, lane = tid & 31;
    const int g = lane >> 2, t = lane & 3;
    const int wc = wid >> 2;
    const int wj = wid & 3;
    const uint32_t quad = lane >> 3, rin = lane & 7;
    const uint32_t a_lane = (((quad & 1) * 8 + rin) * ST + (quad >> 1) * 8) * 2;
    const uint32_t b_lane = (((quad >> 1) * 8 + rin) * ST + (quad & 1) * 8) * 2;

    const uint32_t sqb = smem_u32(sQ), skb = smem_u32(sK);
    const uint32_t svb = smem_u32(sV), spb = smem_u32(sP);

    auto load_kv = [&](int ch, int buf) {
        const int i0 = ch * 64;
        const char* Kg = (const char*)(g_kt + ((size_t)m * 1024 + i0) * 64);
        const char* Vg = (const char*)(g_v + (size_t)m * 64 * 1024 + i0);
        const uint32_t kb0 = skb + buf * KVB;
        const uint32_t vb0 = svb + buf * KVB;
        for (int e = tid; e < 512; e += 256) {
            int r = e >> 3, u = e & 7;
            CP_ASYNC16(kb0 + (r * ST) * 2 + u * 16, Kg + r * 128 + u * 16);
        }
        for (int e = tid; e < 512; e += 256) {
            int r = e >> 3, u = e & 7;
            CP_ASYNC16(vb0 + (r * ST) * 2 + u * 16, Vg + r * 2048 + u * 16);
        }
        CP_COMMIT();
    };

    {
        const char* Qg = (const char*)(g_qt + ((size_t)m * 1024 + jt * 128) * 64);
        for (int e = tid; e < 1024; e += 256) {
            int r = e >> 3, u = e & 7;
            CP_ASYNC16(sqb + (r * ST) * 2 + u * 16, Qg + r * 128 + u * 16);
        }
        CP_COMMIT();
    }
    load_kv(0, 0);
    CP_WAIT1();
    __syncthreads();

    uint32_t qf[4][4];
    {
        const uint32_t qa = sqb + (wid * 16 * ST) * 2 + a_lane;
#pragma unroll
        for (int ks = 0; ks < 4; ks++)
            LDSM_X4(qf[ks][0], qf[ks][1], qf[ks][2], qf[ks][3], qa + ks * 32);
    }

    float accO[2][4][4];
#pragma unroll
    for (int mf = 0; mf < 2; mf++)
#pragma unroll
        for (int nf = 0; nf < 4; nf++)
#pragma unroll
            for (int e = 0; e < 4; e++) accO[mf][nf][e] = 0.f;

    float m_run[2] = {-1e30f, -1e30f};
    float l_t[2]   = {0.f, 0.f};
    const int jr = wid * 16 + g;

    for (int ch = 0; ch < 16; ch++) {
        const int buf = ch & 1;
        if (ch + 1 < 16) { load_kv(ch + 1, buf ^ 1); CP_WAIT1(); }
        else             { CP_WAIT0(); }
        __syncthreads();

        float accS[8][4];
#pragma unroll
        for (int nf = 0; nf < 8; nf++)
#pragma unroll
            for (int e = 0; e < 4; e++) accS[nf][e] = 0.f;

        const uint32_t kb = skb + buf * KVB + b_lane;
#pragma unroll
        for (int ks = 0; ks < 4; ks++) {
            const uint32_t kofs = ks * 32;
#pragma unroll
            for (int pf = 0; pf < 4; pf++) {
                uint32_t b0, b1, b2, b3;
                LDSM_X4(b0, b1, b2, b3, kb + pf * 16 * ST * 2 + kofs);
                MMA_F16(accS[2*pf][0], accS[2*pf][1], accS[2*pf][2], accS[2*pf][3],
                        qf[ks][0], qf[ks][1], qf[ks][2], qf[ks][3], b0, b1);
                MMA_F16(accS[2*pf+1][0], accS[2*pf+1][1], accS[2*pf+1][2], accS[2*pf+1][3],
                        qf[ks][0], qf[ks][1], qf[ks][2], qf[ks][3], b2, b3);
            }
        }

        float cmax[2] = {-1e30f, -1e30f};
#pragma unroll
        for (int nf = 0; nf < 8; nf++) {
            cmax[0] = fmaxf(cmax[0], fmaxf(accS[nf][0], accS[nf][1]));
            cmax[1] = fmaxf(cmax[1], fmaxf(accS[nf][2], accS[nf][3]));
        }
#pragma unroll
        for (int o = 1; o <= 2; o <<= 1) {
            cmax[0] = fmaxf(cmax[0], __shfl_xor_sync(0xffffffffu, cmax[0], o));
            cmax[1] = fmaxf(cmax[1], __shfl_xor_sync(0xffffffffu, cmax[1], o));
        }
        float mn0 = fmaxf(m_run[0], cmax[0]);
        float mn1 = fmaxf(m_run[1], cmax[1]);
        float sc0 = __expf(m_run[0] - mn0);
        float sc1 = __expf(m_run[1] - mn1);
        m_run[0] = mn0; m_run[1] = mn1;

        float psum[2] = {0.f, 0.f};
#pragma unroll
        for (int nf = 0; nf < 8; nf++) {
            accS[nf][0] = __expf(accS[nf][0] - mn0);
            accS[nf][1] = __expf(accS[nf][1] - mn0);
            accS[nf][2] = __expf(accS[nf][2] - mn1);
            accS[nf][3] = __expf(accS[nf][3] - mn1);
            psum[0] += accS[nf][0] + accS[nf][1];
            psum[1] += accS[nf][2] + accS[nf][3];
        }
        l_t[0] = l_t[0] * sc0 + psum[0];
        l_t[1] = l_t[1] * sc1 + psum[1];

        if (t == 0) { sScale[jr] = sc0; sScale[jr + 8] = sc1; }
#pragma unroll
        for (int nf = 0; nf < 8; nf++) {
            int ic = nf * 8 + 2 * t;
            *(__half2*)&sP[jr * ST + ic]       = __floats2half2_rn(accS[nf][0], accS[nf][1]);
            *(__half2*)&sP[(jr + 8) * ST + ic] = __floats2half2_rn(accS[nf][2], accS[nf][3]);
        }
        __syncthreads();

#pragma unroll
        for (int nf = 0; nf < 4; nf++) {
            float s0 = sScale[wj * 32 + nf * 8 + 2 * t];
            float s1 = sScale[wj * 32 + nf * 8 + 2 * t + 1];
#pragma unroll
            for (int mf = 0; mf < 2; mf++) {
                accO[mf][nf][0] *= s0; accO[mf][nf][1] *= s1;
                accO[mf][nf][2] *= s0; accO[mf][nf][3] *= s1;
            }
        }
        const uint32_t va = svb + buf * KVB + (wc * 32 * ST) * 2 + a_lane;
        const uint32_t pb = spb + (wj * 32 * ST) * 2 + b_lane;
#pragma unroll
        for (int ks = 0; ks < 4; ks++) {
            const uint32_t kofs = ks * 32;
            uint32_t af[2][4];
#pragma unroll
            for (int mf = 0; mf < 2; mf++)
                LDSM_X4(af[mf][0], af[mf][1], af[mf][2], af[mf][3],
                        va + mf * 16 * ST * 2 + kofs);
#pragma unroll
            for (int pf = 0; pf < 2; pf++) {
                uint32_t b0, b1, b2, b3;
                LDSM_X4(b0, b1, b2, b3, pb + pf * 16 * ST * 2 + kofs);
#pragma unroll
                for (int mf = 0; mf < 2; mf++) {
                    MMA_F16(accO[mf][2*pf][0], accO[mf][2*pf][1], accO[mf][2*pf][2], accO[mf][2*pf][3],
                            af[mf][0], af[mf][1], af[mf][2], af[mf][3], b0, b1);
                    MMA_F16(accO[mf][2*pf+1][0], accO[mf][2*pf+1][1], accO[mf][2*pf+1][2], accO[mf][2*pf+1][3],
                            af[mf][0], af[mf][1], af[mf][2], af[mf][3], b2, b3);
                }
            }
        }
        __syncthreads();
    }

#pragma unroll
    for (int o = 1; o <= 2; o <<= 1) {
        l_t[0] += __shfl_xor_sync(0xffffffffu, l_t[0], o);
        l_t[1] += __shfl_xor_sync(0xffffffffu, l_t[1], o);
    }
    if (t == 0) {
        sScale[jr]     = 1.f / l_t[0];
        sScale[jr + 8] = 1.f / l_t[1];
    }
    __syncthreads();

    const int n = m >> 2, hh = m & 3;
    const int b = n / 9, rem = n % 9;
    const int wh = rem / 3, ww = rem % 3;
#pragma unroll
    for (int nf = 0; nf < 4; nf++) {
#pragma unroll
        for (int e = 0; e < 2; e++) {
            const int jl = wj * 32 + nf * 8 + 2 * t + e;
            const float inv = sScale[jl];
            const int j = jt * 128 + jl;
            const int h = wh * 32 + (j >> 5), w = ww * 32 + (j & 31);
            __half* dst = g_ocl + (((size_t)b * 98 + h + 1) * 98 + (w + 1)) * 256 + hh * 64;
#pragma unroll
            for (int mf = 0; mf < 2; mf++) {
                const int c0 = wc * 32 + mf * 16 + g;
                dst[c0]     = __float2half_rn(accO[mf][nf][0 + e] * inv);
                dst[c0 + 8] = __float2half_rn(accO[mf][nf][2 + e] * inv);
            }
        }
    }
}

// ===========================================================================
extern "C" void kernel_launch(void* const* d_in, const int* in_sizes, int n_in,
                              void* d_out, int out_size)
{
    (void)in_sizes; (void)n_in; (void)out_size;
    const float* x  = (const float*)d_in[0];
    const float* W1 = (const float*)d_in[1];
    const float* b1 = (const float*)d_in[2];
    const float* W2 = (const float*)d_in[3];
    const float* b2 = (const float*)d_in[4];
    float* out = (float*)d_out;

    const int CONV_SMEM = 2 * (9 * 128 * 64 + 340 * 64);   // 190976 B
    cudaFuncSetAttribute(conv_mma_kernel<512, 768, 0>,
                         cudaFuncAttributeMaxDynamicSharedMemorySize, CONV_SMEM);
    cudaFuncSetAttribute(conv_mma_kernel<256, 512, 1>,
                         cudaFuncAttributeMaxDynamicSharedMemorySize, CONV_SMEM);

    const int ATTN_SMEM = (128 + 2 * 64 + 2 * 64 + 128) * 72 * 2 + 128 * 4;  // 74240 B
    cudaFuncSetAttribute(fused_attn_kernel,
                         cudaFuncAttributeMaxDynamicSharedMemorySize, ATTN_SMEM);

    // packs (merged launches)
    const int FB_TOTAL = 2 * 388 * 64 + 2 * 388 * 32;
    fill_border_all_kernel<<<(FB_TOTAL + 255) / 256, 256>>>();
    pack_cl_kernel<<<dim3(96, 16, 2), 256>>>(x);
    const int RW_TOTAL = 9 * 768 * 512 + 9 * 512 * 256;
    repack_w_all_kernel<<<(RW_TOTAL + 255) / 256, 256>>>(W1, W2);

    // conv1 + ReLU -> packed Q/K/V (fp16 mma, halo-resident)
    conv_mma_kernel<512, 768, 0><<<dim3(72, 6), 256, CONV_SMEM>>>(b1, nullptr, nullptr);

    // fused attention -> g_ocl (fp16 channels-last conv2 input)
    fused_attn_kernel<<<dim3(8, 72), 256, ATTN_SMEM>>>();

    // conv2 + residual (fp16 mma, halo-resident, fp32 epilogue)
    conv_mma_kernel<256, 512, 1><<<dim3(72, 4), 256, CONV_SMEM>>>(b2, x, out);
}